// round 16
// baseline (speedup 1.0000x reference)
#include <cuda_runtime.h>
#include <cuda_fp16.h>
#include <math.h>
#include <stdint.h>

#define Bb 8
#define Nn 4096
#define Dd 512
#define Mm (Bb*Nn)      // 32768
#define QKVC 1536
#define KVCH 2          // split-K chunks for kv GEMM

// ---------------- scratch (__device__ globals; allocation-free rule) --------
__device__ __half g_phi_hi[(size_t)Mm*Dd];
__device__ __half g_W_hi[(size_t)QKVC*Dd];     // permuted rows (rope pairs adjacent)
__device__ float  g_bias[QKVC];                 // same permutation
__device__ __half g_q_hi[(size_t)Mm*Dd];
__device__ __half g_kT_hi[(size_t)Bb*Dd*Nn];
__device__ __half g_vT_hi[(size_t)Bb*Dd*Nn];
__device__ float  g_kvp[(size_t)Bb*KVCH*Dd*Dd]; // split-K partials
__device__ __half g_kvT_hi[(size_t)Bb*Dd*Dd];

// ---------------- helpers ----------------------------------------------------
__device__ __forceinline__ uint32_t smem_u32(const void* p) {
    uint32_t a;
    asm("{ .reg .u64 t; cvta.to.shared.u64 t, %1; cvt.u32.u64 %0, t; }" : "=r"(a) : "l"(p));
    return a;
}
__device__ __forceinline__ void cp16(uint32_t dst, const void* src) {
    asm volatile("cp.async.cg.shared.global [%0], [%1], 16;" :: "r"(dst), "l"(src) : "memory");
}
__device__ __forceinline__ void ldsm4(uint32_t* r, uint32_t addr) {
    asm volatile("ldmatrix.sync.aligned.m8n8.x4.shared.b16 {%0,%1,%2,%3}, [%4];"
                 : "=r"(r[0]), "=r"(r[1]), "=r"(r[2]), "=r"(r[3]) : "r"(addr));
}
__device__ __forceinline__ void mma16816(float* d, const uint32_t* a, const uint32_t* b) {
    asm volatile(
        "mma.sync.aligned.m16n8k16.row.col.f32.f16.f16.f32 "
        "{%0,%1,%2,%3}, {%4,%5,%6,%7}, {%8,%9}, {%0,%1,%2,%3};"
        : "+f"(d[0]), "+f"(d[1]), "+f"(d[2]), "+f"(d[3])
        : "r"(a[0]), "r"(a[1]), "r"(a[2]), "r"(a[3]), "r"(b[0]), "r"(b[1]));
}
__device__ __forceinline__ uint32_t pack2h(float a, float b) {
    return (uint32_t)__half_as_ushort(__float2half_rn(a)) |
           ((uint32_t)__half_as_ushort(__float2half_rn(b)) << 16);
}

// 64-deep k-step stages: 64 fp16 = 128B data + 16B pad per row
#define RB 144           // row stride bytes (9 x 16B segments; 9 mod 8 = 1 -> conflict-free)
#define STG (128*RB)     // 18432 B per operand stage
#define SLOT (2*STG)     // A+B per stage = 36864 B
#define SMEMTOT (3*SLOT) // 110592 B, 3-stage ring

// ---------------------------------------------------------------------------
// Generic warp-MMA fp16 GEMM: D[m,n] = Ahi[m,:] . Bhi[n,:]
// Block tile 128x128x64, 8 warps, 3-stage cp.async ring (2 stages in flight).
// blockIdx.z = (batch << bzShift) | chunk.
// ---------------------------------------------------------------------------
__global__ __launch_bounds__(256, 2) void mma_gemm1(
    const __half* __restrict__ Ahi, const __half* __restrict__ Bhi,
    int Kchunk, int ldab, int bzShift, size_t aBS, size_t bBS,
    float* __restrict__ C, size_t cBS, int ldc)
{
    extern __shared__ __align__(16) char smem[];
    const uint32_t sbase = smem_u32(smem);
    const int tid  = threadIdx.x;
    const int lane = tid & 31;
    const int wid  = tid >> 5;
    const int wm   = wid >> 2;
    const int wn   = wid & 3;
    const int n0 = blockIdx.x * 128;
    const int m0 = blockIdx.y * 128;
    const int bz = blockIdx.z;
    const int b  = bz >> bzShift;
    const int koff = (bz & ((1 << bzShift) - 1)) * Kchunk;

    const int S = Kchunk >> 6;          // 64-deep stages
    const __half* Ap = Ahi + (size_t)b * aBS;
    const __half* Bp = Bhi + (size_t)b * bBS;

    const int lr = tid >> 1;            // row 0..127
    const int lc = (tid & 1) * 4;       // 16B chunk 0..3 or 4..7

    auto load = [&](int s) {
        int slot = s % 3;
        int k0 = koff + (s << 6);
        uint32_t da = sbase + slot * SLOT;
        uint32_t db = da + STG;
        const __half* ag = Ap + (size_t)(m0 + lr) * ldab + k0 + lc * 8;
        const __half* bg = Bp + (size_t)(n0 + lr) * ldab + k0 + lc * 8;
#pragma unroll
        for (int j = 0; j < 4; j++) {
            cp16(da + lr * RB + (lc + j) * 16, ag + j * 8);
            cp16(db + lr * RB + (lc + j) * 16, bg + j * 8);
        }
        asm volatile("cp.async.commit_group;" ::: "memory");
    };

    const uint32_t laA = ((lane & 7) + ((lane >> 3) & 1) * 8) * RB + (lane >> 4) * 16;
    const uint32_t laB = ((lane & 7) + (lane >> 4) * 8) * RB + ((lane >> 3) & 1) * 16;

    float acc[4][4][4] = {};
    load(0); load(1);

    for (int s = 0; s < S; s++) {
        asm volatile("cp.async.wait_group 1;" ::: "memory");
        __syncthreads();
        if (s + 2 < S) load(s + 2);
        int slot = s % 3;
        uint32_t sa  = sbase + slot * SLOT;
        uint32_t sbB = sa + STG;
#pragma unroll
        for (int ks = 0; ks < 4; ks++) {
            uint32_t a[4][4], bfr[2][4];
#pragma unroll
            for (int mf = 0; mf < 4; mf++)
                ldsm4(a[mf], sa + (wm * 64 + mf * 16) * RB + ks * 32 + laA);
#pragma unroll
            for (int bp = 0; bp < 2; bp++)
                ldsm4(bfr[bp], sbB + (wn * 32 + bp * 16) * RB + ks * 32 + laB);
#pragma unroll
            for (int mf = 0; mf < 4; mf++)
#pragma unroll
                for (int nf = 0; nf < 4; nf++)
                    mma16816(acc[mf][nf], a[mf], &bfr[nf >> 1][(nf & 1) * 2]);
        }
    }

    const int g = lane >> 2;
    const int cq = (lane & 3) * 2;
#pragma unroll
    for (int mf = 0; mf < 4; mf++)
#pragma unroll
        for (int nf = 0; nf < 4; nf++) {
            int row = m0 + wm * 64 + mf * 16 + g;
            int col = n0 + wn * 32 + nf * 8 + cq;
            float* dst = C + (size_t)bz * cBS + (size_t)row * ldc + col;
            *(float2*)dst = make_float2(acc[mf][nf][0], acc[mf][nf][1]);
            *(float2*)(dst + 8 * ldc) = make_float2(acc[mf][nf][2], acc[mf][nf][3]);
        }
}

// ---------------------------------------------------------------------------
// Fused QKV GEMM (1-term A): qkv = phi @ Wperm^T + bias, per-region epilogue:
//   region 0 (cols [0,512)):    q -> rope+scale -> g_q_hi row-major fp16
//   region 1 (cols [512,1024)): k -> rope -> smem transpose -> g_kT_hi [b,d,n]
//   region 2 (cols [1024,1536)):v -> *weights -> transpose -> g_vT_hi [b,d,n]
// W rows permuted so rope pair (h,h+256) = adjacent cols (2h,2h+1); d-order
// permutation cancels in the q.kv contraction.
// ---------------------------------------------------------------------------
__global__ __launch_bounds__(256, 2) void mma_gemm_qkv(
    const __half* __restrict__ Ahi, const __half* __restrict__ Bhi,
    const float* __restrict__ bias,
    const float* __restrict__ coords, const float* __restrict__ weights,
    const float* __restrict__ Wrot)
{
    extern __shared__ __align__(16) char smem[];
    const uint32_t sbase = smem_u32(smem);
    const int tid  = threadIdx.x;
    const int lane = tid & 31;
    const int wid  = tid >> 5;
    const int wm   = wid >> 2;
    const int wn   = wid & 3;
    const int n0 = blockIdx.x * 128;
    const int m0 = blockIdx.y * 128;

    const int S = Dd >> 6;           // 8 stages of K=64
    const int lr = tid >> 1;
    const int lc = (tid & 1) * 4;

    auto load = [&](int s) {
        int slot = s % 3;
        int k0 = s << 6;
        uint32_t da = sbase + slot * SLOT;
        uint32_t db = da + STG;
        const __half* ag = Ahi + (size_t)(m0 + lr) * Dd + k0 + lc * 8;
        const __half* bg = Bhi + (size_t)(n0 + lr) * Dd + k0 + lc * 8;
#pragma unroll
        for (int j = 0; j < 4; j++) {
            cp16(da + lr * RB + (lc + j) * 16, ag + j * 8);
            cp16(db + lr * RB + (lc + j) * 16, bg + j * 8);
        }
        asm volatile("cp.async.commit_group;" ::: "memory");
    };

    const uint32_t laA = ((lane & 7) + ((lane >> 3) & 1) * 8) * RB + (lane >> 4) * 16;
    const uint32_t laB = ((lane & 7) + (lane >> 4) * 8) * RB + ((lane >> 3) & 1) * 16;

    float acc[4][4][4] = {};
    load(0); load(1);

    for (int s = 0; s < S; s++) {
        asm volatile("cp.async.wait_group 1;" ::: "memory");
        __syncthreads();
        if (s + 2 < S) load(s + 2);
        int slot = s % 3;
        uint32_t sa  = sbase + slot * SLOT;
        uint32_t sbB = sa + STG;
#pragma unroll
        for (int ks = 0; ks < 4; ks++) {
            uint32_t a[4][4], bfr[2][4];
#pragma unroll
            for (int mf = 0; mf < 4; mf++)
                ldsm4(a[mf], sa + (wm * 64 + mf * 16) * RB + ks * 32 + laA);
#pragma unroll
            for (int bp = 0; bp < 2; bp++)
                ldsm4(bfr[bp], sbB + (wn * 32 + bp * 16) * RB + ks * 32 + laB);
#pragma unroll
            for (int mf = 0; mf < 4; mf++)
#pragma unroll
                for (int nf = 0; nf < 4; nf++)
                    mma16816(acc[mf][nf], a[mf], &bfr[nf >> 1][(nf & 1) * 2]);
        }
    }

    // drain pending cp.async before smem reuse
    asm volatile("cp.async.wait_group 0;" ::: "memory");
    __syncthreads();

    const int g = lane >> 2;
    const int cq = (lane & 3) * 2;
    const int region = n0 >> 9;      // 0 q, 1 k, 2 v
    const float scale = 0.04419417382415922f;   // 1/sqrt(512)

    if (region == 0) {
        // q: rope + scale, direct row-major fp16 store
#pragma unroll
        for (int mf = 0; mf < 4; mf++) {
            int r0 = m0 + wm * 64 + mf * 16 + g;
            float cx0 = coords[r0*3], cy0 = coords[r0*3+1], cz0 = coords[r0*3+2];
            float cx1 = coords[(r0+8)*3], cy1 = coords[(r0+8)*3+1], cz1 = coords[(r0+8)*3+2];
#pragma unroll
            for (int nf = 0; nf < 4; nf++) {
                int col = n0 + wn * 32 + nf * 8 + cq;
                int h = col >> 1;
                float w0 = Wrot[h*3], w1 = Wrot[h*3+1], w2 = Wrot[h*3+2];
                float b0 = bias[col], b1 = bias[col+1];
                float s0, c0, s1, c1;
                __sincosf(cx0*w0 + cy0*w1 + cz0*w2, &s0, &c0);
                __sincosf(cx1*w0 + cy1*w1 + cz1*w2, &s1, &c1);
                float qa = acc[mf][nf][0] + b0, qb = acc[mf][nf][1] + b1;
                *(uint32_t*)(g_q_hi + (size_t)r0*Dd + col) =
                    pack2h((qa*c0 - qb*s0)*scale, (qa*s0 + qb*c0)*scale);
                qa = acc[mf][nf][2] + b0; qb = acc[mf][nf][3] + b1;
                *(uint32_t*)(g_q_hi + (size_t)(r0+8)*Dd + col) =
                    pack2h((qa*c1 - qb*s1)*scale, (qa*s1 + qb*c1)*scale);
            }
        }
    } else {
        uint16_t (*st)[136] = (uint16_t(*)[136])smem;
        const int cbase = (region == 1) ? 512 : 1024;
        if (region == 1) {
#pragma unroll
            for (int mf = 0; mf < 4; mf++) {
                int r0 = m0 + wm * 64 + mf * 16 + g;
                int lr0 = r0 - m0;
                float cx0 = coords[r0*3], cy0 = coords[r0*3+1], cz0 = coords[r0*3+2];
                float cx1 = coords[(r0+8)*3], cy1 = coords[(r0+8)*3+1], cz1 = coords[(r0+8)*3+2];
#pragma unroll
                for (int nf = 0; nf < 4; nf++) {
                    int col = n0 + wn * 32 + nf * 8 + cq;
                    int h = (col - 512) >> 1;
                    int lcol = col - n0;
                    float w0 = Wrot[h*3], w1 = Wrot[h*3+1], w2 = Wrot[h*3+2];
                    float b0 = bias[col], b1 = bias[col+1];
                    float s0, c0, s1, c1;
                    __sincosf(cx0*w0 + cy0*w1 + cz0*w2, &s0, &c0);
                    __sincosf(cx1*w0 + cy1*w1 + cz1*w2, &s1, &c1);
                    float ka = acc[mf][nf][0] + b0, kb = acc[mf][nf][1] + b1;
                    st[lcol][lr0]     = __half_as_ushort(__float2half_rn(ka*c0 - kb*s0));
                    st[lcol+1][lr0]   = __half_as_ushort(__float2half_rn(ka*s0 + kb*c0));
                    ka = acc[mf][nf][2] + b0; kb = acc[mf][nf][3] + b1;
                    st[lcol][lr0+8]   = __half_as_ushort(__float2half_rn(ka*c1 - kb*s1));
                    st[lcol+1][lr0+8] = __half_as_ushort(__float2half_rn(ka*s1 + kb*c1));
                }
            }
        } else {
#pragma unroll
            for (int mf = 0; mf < 4; mf++) {
                int r0 = m0 + wm * 64 + mf * 16 + g;
                int lr0 = r0 - m0;
                float wg0 = weights[r0], wg1 = weights[r0 + 8];
#pragma unroll
                for (int nf = 0; nf < 4; nf++) {
                    int col = n0 + wn * 32 + nf * 8 + cq;
                    int lcol = col - n0;
                    float b0 = bias[col], b1 = bias[col+1];
                    st[lcol][lr0]     = __half_as_ushort(__float2half_rn((acc[mf][nf][0]+b0)*wg0));
                    st[lcol+1][lr0]   = __half_as_ushort(__float2half_rn((acc[mf][nf][1]+b1)*wg0));
                    st[lcol][lr0+8]   = __half_as_ushort(__float2half_rn((acc[mf][nf][2]+b0)*wg1));
                    st[lcol+1][lr0+8] = __half_as_ushort(__float2half_rn((acc[mf][nf][3]+b1)*wg1));
                }
            }
        }
        __syncthreads();
        // transposed coalesced write: [b, d, n]
        const int dl = tid >> 1;
        const int j0 = (tid & 1) * 64;
        const int bidx = m0 >> 12;
        const int dcol = (n0 - cbase) + dl;
        __half* dstb = (region == 1) ? g_kT_hi : g_vT_hi;
        __half* dst = dstb + ((size_t)bidx * Dd + dcol) * Nn + (m0 & 4095) + j0;
#pragma unroll
        for (int kk = 0; kk < 8; kk++)
            *(uint4*)(dst + kk * 8) = *(uint4*)&st[dl][j0 + kk * 8];
    }
}

// ---------------------------------------------------------------------------
// Sum KVCH split-K partial kv slices, emit fp16 (B operand of GEMM3).
// ---------------------------------------------------------------------------
__global__ __launch_bounds__(256) void reduce_pack_kv()
{
    size_t i = ((size_t)blockIdx.x * 256 + threadIdx.x) * 2;
    size_t b   = i >> 18;
    size_t off = i & 262143;
    const float* base = g_kvp + ((size_t)b * KVCH) * 262144 + off;
    float s0 = 0.f, s1 = 0.f;
#pragma unroll
    for (int c = 0; c < KVCH; c++) {
        float2 v = *(const float2*)(base + (size_t)c * 262144);
        s0 += v.x; s1 += v.y;
    }
    size_t o = (size_t)b * 262144 + off;
    *(uint32_t*)(g_kvT_hi + o) = pack2h(s0, s1);
}

// ---------------------------------------------------------------------------
__global__ __launch_bounds__(256) void pack_phi(const float* __restrict__ phi)
{
    size_t i = ((size_t)blockIdx.x * 256 + threadIdx.x) * 4;
    float4 x = *(const float4*)(phi + i);
    *(uint32_t*)(g_phi_hi + i)     = pack2h(x.x, x.y);
    *(uint32_t*)(g_phi_hi + i + 2) = pack2h(x.z, x.w);
}

// Permuted: q/k regions interleave rope pairs -> out row 2h <- h, 2h+1 <- h+256
__global__ __launch_bounds__(128) void pack_W(
    const float* __restrict__ Wq, const float* __restrict__ bq,
    const float* __restrict__ Wk, const float* __restrict__ bk,
    const float* __restrict__ Wv, const float* __restrict__ bv)
{
    int r = blockIdx.x, t = threadIdx.x;
    const float* src; const float* bs; int sr;
    if (r < 512)       { src = Wq; bs = bq; int h = r >> 1;         sr = (r & 1) ? h + 256 : h; }
    else if (r < 1024) { src = Wk; bs = bk; int h = (r - 512) >> 1; sr = ((r - 512) & 1) ? h + 256 : h; }
    else               { src = Wv; bs = bv; sr = r - 1024; }
    float4 x = *(const float4*)(src + (size_t)sr * Dd + t * 4);
    size_t o = (size_t)r * Dd + t * 4;
    *(uint32_t*)(g_W_hi + o)     = pack2h(x.x, x.y);
    *(uint32_t*)(g_W_hi + o + 2) = pack2h(x.z, x.w);
    if (t == 0) g_bias[r] = bs[sr];
}

// ---------------------------------------------------------------------------
extern "C" void kernel_launch(void* const* d_in, const int* in_sizes, int n_in,
                              void* d_out, int out_size)
{
    (void)in_sizes; (void)n_in; (void)out_size;
    const float* phi     = (const float*)d_in[0];
    const float* coords  = (const float*)d_in[1];
    const float* weights = (const float*)d_in[2];
    const float* Wq      = (const float*)d_in[3];
    const float* bq      = (const float*)d_in[4];
    const float* Wk      = (const float*)d_in[5];
    const float* bk      = (const float*)d_in[6];
    const float* Wv      = (const float*)d_in[7];
    const float* bv      = (const float*)d_in[8];
    const float* Wrot    = (const float*)d_in[9];
    float* out = (float*)d_out;

    cudaFuncSetAttribute(mma_gemm1,    cudaFuncAttributeMaxDynamicSharedMemorySize, SMEMTOT);
    cudaFuncSetAttribute(mma_gemm_qkv, cudaFuncAttributeMaxDynamicSharedMemorySize, SMEMTOT);

    __half *phi_hi, *W_hi, *q_hi, *kT_hi, *vT_hi, *kvT_hi;
    float *bias, *kvp;
    cudaGetSymbolAddress((void**)&phi_hi, g_phi_hi);
    cudaGetSymbolAddress((void**)&W_hi,   g_W_hi);
    cudaGetSymbolAddress((void**)&q_hi,   g_q_hi);
    cudaGetSymbolAddress((void**)&kT_hi,  g_kT_hi);
    cudaGetSymbolAddress((void**)&vT_hi,  g_vT_hi);
    cudaGetSymbolAddress((void**)&kvT_hi, g_kvT_hi);
    cudaGetSymbolAddress((void**)&bias,   g_bias);
    cudaGetSymbolAddress((void**)&kvp,    g_kvp);

    pack_phi<<<(Mm * Dd) / 1024, 256>>>(phi);
    pack_W<<<QKVC, 128>>>(Wq, bq, Wk, bk, Wv, bv);

    // fused: qkv GEMM + bias + rope/scale/weights + fp16 pack + k/v transpose
    mma_gemm_qkv<<<dim3(QKVC/128, Mm/128, 1), 256, SMEMTOT>>>(
        phi_hi, W_hi, bias, coords, weights, Wrot);

    // kv split-K: kvp[b,chunk][e,d] = sum_{n in chunk} vT[e,n]*kT[d,n]
    mma_gemm1<<<dim3(Dd/128, Dd/128, Bb*KVCH), 256, SMEMTOT>>>(
        vT_hi, kT_hi, Nn/KVCH, Nn, 1,
        (size_t)Dd*Nn, (size_t)Dd*Nn,
        kvp, (size_t)Dd*Dd, Dd);

    reduce_pack_kv<<<(Bb * Dd * Dd) / 512, 256>>>();

    // out[m,e] = sum_d q[m,d]*kvT[e,d]
    mma_gemm1<<<dim3(Dd/128, Nn/128, Bb), 256, SMEMTOT>>>(
        q_hi, kvT_hi, Dd, Dd, 0,
        (size_t)Nn*Dd, (size_t)Dd*Dd,
        out, (size_t)Nn*Dd, Dd);
}

// round 17
// speedup vs baseline: 1.1063x; 1.1063x over previous
#include <cuda_runtime.h>
#include <cuda_fp16.h>
#include <math.h>
#include <stdint.h>

#define Bb 8
#define Nn 4096
#define Dd 512
#define Mm (Bb*Nn)      // 32768
#define QKVC 1536
#define KVCH 2          // split-K chunks for kv GEMM

// ---------------- scratch (__device__ globals; allocation-free rule) --------
__device__ __half g_phi_hi[(size_t)Mm*Dd];
__device__ __half g_W_hi[(size_t)QKVC*Dd];     // permuted rows (rope pairs adjacent)
__device__ float  g_bias[QKVC];                 // same permutation
__device__ __half g_q_hi[(size_t)Mm*Dd];
__device__ __half g_kT_hi[(size_t)Bb*Dd*Nn];
__device__ __half g_vT_hi[(size_t)Bb*Dd*Nn];
__device__ float  g_kvp[(size_t)Bb*KVCH*Dd*Dd]; // split-K partials
__device__ __half g_kvT_hi[(size_t)Bb*Dd*Dd];

// ---------------- helpers ----------------------------------------------------
__device__ __forceinline__ uint32_t smem_u32(const void* p) {
    uint32_t a;
    asm("{ .reg .u64 t; cvta.to.shared.u64 t, %1; cvt.u32.u64 %0, t; }" : "=r"(a) : "l"(p));
    return a;
}
__device__ __forceinline__ void cp16(uint32_t dst, const void* src) {
    asm volatile("cp.async.cg.shared.global [%0], [%1], 16;" :: "r"(dst), "l"(src) : "memory");
}
__device__ __forceinline__ void ldsm4(uint32_t* r, uint32_t addr) {
    asm volatile("ldmatrix.sync.aligned.m8n8.x4.shared.b16 {%0,%1,%2,%3}, [%4];"
                 : "=r"(r[0]), "=r"(r[1]), "=r"(r[2]), "=r"(r[3]) : "r"(addr));
}
__device__ __forceinline__ void mma16816(float* d, const uint32_t* a, const uint32_t* b) {
    asm volatile(
        "mma.sync.aligned.m16n8k16.row.col.f32.f16.f16.f32 "
        "{%0,%1,%2,%3}, {%4,%5,%6,%7}, {%8,%9}, {%0,%1,%2,%3};"
        : "+f"(d[0]), "+f"(d[1]), "+f"(d[2]), "+f"(d[3])
        : "r"(a[0]), "r"(a[1]), "r"(a[2]), "r"(a[3]), "r"(b[0]), "r"(b[1]));
}
__device__ __forceinline__ uint32_t pack2h(float a, float b) {
    return (uint32_t)__half_as_ushort(__float2half_rn(a)) |
           ((uint32_t)__half_as_ushort(__float2half_rn(b)) << 16);
}

#define RB 80            // row stride bytes (32 fp16 = 64B data + 16B pad)
#define STG (128*RB)     // 10240 B per operand stage
#define SLOT (2*STG)     // A+B per stage
#define SMEMTOT (4*SLOT) // 81920 B

// ---------------------------------------------------------------------------
// Generic warp-MMA fp16 GEMM: D[m,n] = Ahi[m,:] . Bhi[n,:]
// Block tile 128x128x32, 8 warps, 4-stage cp.async ring.
// blockIdx.z = (batch << bzShift) | chunk.
// ---------------------------------------------------------------------------
__global__ __launch_bounds__(256, 2) void mma_gemm1(
    const __half* __restrict__ Ahi, const __half* __restrict__ Bhi,
    int Kchunk, int ldab, int bzShift, size_t aBS, size_t bBS,
    float* __restrict__ C, size_t cBS, int ldc)
{
    extern __shared__ __align__(16) char smem[];
    const uint32_t sbase = smem_u32(smem);
    const int tid  = threadIdx.x;
    const int lane = tid & 31;
    const int wid  = tid >> 5;
    const int wm   = wid >> 2;
    const int wn   = wid & 3;
    const int n0 = blockIdx.x * 128;
    const int m0 = blockIdx.y * 128;
    const int bz = blockIdx.z;
    const int b  = bz >> bzShift;
    const int koff = (bz & ((1 << bzShift) - 1)) * Kchunk;

    const int S = Kchunk >> 5;
    const __half* Ap = Ahi + (size_t)b * aBS;
    const __half* Bp = Bhi + (size_t)b * bBS;

    const int lr = tid >> 1;
    const int lc = (tid & 1) * 2;

    auto load = [&](int s) {
        int k0 = koff + (s << 5);
        uint32_t da = sbase + (s & 3) * SLOT;
        uint32_t db = da + STG;
        const __half* ag = Ap + (size_t)(m0 + lr) * ldab + k0 + lc * 8;
        cp16(da + lr * RB + lc * 16, ag);
        cp16(da + lr * RB + lc * 16 + 16, ag + 8);
        const __half* bg = Bp + (size_t)(n0 + lr) * ldab + k0 + lc * 8;
        cp16(db + lr * RB + lc * 16, bg);
        cp16(db + lr * RB + lc * 16 + 16, bg + 8);
        asm volatile("cp.async.commit_group;" ::: "memory");
    };

    const uint32_t laA = ((lane & 7) + ((lane >> 3) & 1) * 8) * RB + (lane >> 4) * 16;
    const uint32_t laB = ((lane & 7) + (lane >> 4) * 8) * RB + ((lane >> 3) & 1) * 16;

    float acc[4][4][4] = {};
    load(0); load(1); load(2);

    for (int s = 0; s < S; s++) {
        asm volatile("cp.async.wait_group 2;" ::: "memory");
        __syncthreads();
        if (s + 3 < S) load(s + 3);
        uint32_t sa  = sbase + (s & 3) * SLOT;
        uint32_t sbB = sa + STG;
#pragma unroll
        for (int ks = 0; ks < 2; ks++) {
            uint32_t a[4][4], bfr[2][4];
#pragma unroll
            for (int mf = 0; mf < 4; mf++)
                ldsm4(a[mf], sa + (wm * 64 + mf * 16) * RB + ks * 32 + laA);
#pragma unroll
            for (int bp = 0; bp < 2; bp++)
                ldsm4(bfr[bp], sbB + (wn * 32 + bp * 16) * RB + ks * 32 + laB);
#pragma unroll
            for (int mf = 0; mf < 4; mf++)
#pragma unroll
                for (int nf = 0; nf < 4; nf++)
                    mma16816(acc[mf][nf], a[mf], &bfr[nf >> 1][(nf & 1) * 2]);
        }
    }

    const int g = lane >> 2;
    const int cq = (lane & 3) * 2;
#pragma unroll
    for (int mf = 0; mf < 4; mf++)
#pragma unroll
        for (int nf = 0; nf < 4; nf++) {
            int row = m0 + wm * 64 + mf * 16 + g;
            int col = n0 + wn * 32 + nf * 8 + cq;
            float* dst = C + (size_t)bz * cBS + (size_t)row * ldc + col;
            *(float2*)dst = make_float2(acc[mf][nf][0], acc[mf][nf][1]);
            *(float2*)(dst + 8 * ldc) = make_float2(acc[mf][nf][2], acc[mf][nf][3]);
        }
}

// ---------------------------------------------------------------------------
// Fused QKV GEMM (1-term A): qkv = phi @ Wperm^T + bias, per-region epilogue:
//   region 0 (cols [0,512)):    q -> rope+scale -> g_q_hi row-major fp16
//   region 1 (cols [512,1024)): k -> rope -> smem transpose -> g_kT_hi [b,d,n]
//   region 2 (cols [1024,1536)):v -> *weights -> transpose -> g_vT_hi [b,d,n]
// W rows permuted so rope pair (h,h+256) = adjacent cols (2h,2h+1); d-order
// permutation cancels in the q.kv contraction.
// ---------------------------------------------------------------------------
__global__ __launch_bounds__(256, 2) void mma_gemm_qkv(
    const __half* __restrict__ Ahi, const __half* __restrict__ Bhi,
    const float* __restrict__ bias,
    const float* __restrict__ coords, const float* __restrict__ weights,
    const float* __restrict__ Wrot)
{
    extern __shared__ __align__(16) char smem[];
    const uint32_t sbase = smem_u32(smem);
    const int tid  = threadIdx.x;
    const int lane = tid & 31;
    const int wid  = tid >> 5;
    const int wm   = wid >> 2;
    const int wn   = wid & 3;
    const int n0 = blockIdx.x * 128;
    const int m0 = blockIdx.y * 128;

    const int S = Dd >> 5;           // 16
    const int lr = tid >> 1;
    const int lc = (tid & 1) * 2;

    auto load = [&](int s) {
        int k0 = s << 5;
        uint32_t da = sbase + (s & 3) * SLOT;
        uint32_t db = da + STG;
        const __half* ag = Ahi + (size_t)(m0 + lr) * Dd + k0 + lc * 8;
        cp16(da + lr * RB + lc * 16, ag);
        cp16(da + lr * RB + lc * 16 + 16, ag + 8);
        const __half* bg = Bhi + (size_t)(n0 + lr) * Dd + k0 + lc * 8;
        cp16(db + lr * RB + lc * 16, bg);
        cp16(db + lr * RB + lc * 16 + 16, bg + 8);
        asm volatile("cp.async.commit_group;" ::: "memory");
    };

    const uint32_t laA = ((lane & 7) + ((lane >> 3) & 1) * 8) * RB + (lane >> 4) * 16;
    const uint32_t laB = ((lane & 7) + (lane >> 4) * 8) * RB + ((lane >> 3) & 1) * 16;

    float acc[4][4][4] = {};
    load(0); load(1); load(2);

    for (int s = 0; s < S; s++) {
        asm volatile("cp.async.wait_group 2;" ::: "memory");
        __syncthreads();
        if (s + 3 < S) load(s + 3);
        uint32_t sa  = sbase + (s & 3) * SLOT;
        uint32_t sbB = sa + STG;
#pragma unroll
        for (int ks = 0; ks < 2; ks++) {
            uint32_t a[4][4], bfr[2][4];
#pragma unroll
            for (int mf = 0; mf < 4; mf++)
                ldsm4(a[mf], sa + (wm * 64 + mf * 16) * RB + ks * 32 + laA);
#pragma unroll
            for (int bp = 0; bp < 2; bp++)
                ldsm4(bfr[bp], sbB + (wn * 32 + bp * 16) * RB + ks * 32 + laB);
#pragma unroll
            for (int mf = 0; mf < 4; mf++)
#pragma unroll
                for (int nf = 0; nf < 4; nf++)
                    mma16816(acc[mf][nf], a[mf], &bfr[nf >> 1][(nf & 1) * 2]);
        }
    }

    // drain pending cp.async before smem reuse
    asm volatile("cp.async.wait_group 0;" ::: "memory");
    __syncthreads();

    const int g = lane >> 2;
    const int cq = (lane & 3) * 2;
    const int region = n0 >> 9;      // 0 q, 1 k, 2 v
    const float scale = 0.04419417382415922f;   // 1/sqrt(512)

    if (region == 0) {
        // q: rope + scale, direct row-major fp16 store
#pragma unroll
        for (int mf = 0; mf < 4; mf++) {
            int r0 = m0 + wm * 64 + mf * 16 + g;
            float cx0 = coords[r0*3], cy0 = coords[r0*3+1], cz0 = coords[r0*3+2];
            float cx1 = coords[(r0+8)*3], cy1 = coords[(r0+8)*3+1], cz1 = coords[(r0+8)*3+2];
#pragma unroll
            for (int nf = 0; nf < 4; nf++) {
                int col = n0 + wn * 32 + nf * 8 + cq;
                int h = col >> 1;
                float w0 = Wrot[h*3], w1 = Wrot[h*3+1], w2 = Wrot[h*3+2];
                float b0 = bias[col], b1 = bias[col+1];
                float s0, c0, s1, c1;
                __sincosf(cx0*w0 + cy0*w1 + cz0*w2, &s0, &c0);
                __sincosf(cx1*w0 + cy1*w1 + cz1*w2, &s1, &c1);
                float qa = acc[mf][nf][0] + b0, qb = acc[mf][nf][1] + b1;
                *(uint32_t*)(g_q_hi + (size_t)r0*Dd + col) =
                    pack2h((qa*c0 - qb*s0)*scale, (qa*s0 + qb*c0)*scale);
                qa = acc[mf][nf][2] + b0; qb = acc[mf][nf][3] + b1;
                *(uint32_t*)(g_q_hi + (size_t)(r0+8)*Dd + col) =
                    pack2h((qa*c1 - qb*s1)*scale, (qa*s1 + qb*c1)*scale);
            }
        }
    } else {
        uint16_t (*st)[136] = (uint16_t(*)[136])smem;
        const int cbase = (region == 1) ? 512 : 1024;
        if (region == 1) {
#pragma unroll
            for (int mf = 0; mf < 4; mf++) {
                int r0 = m0 + wm * 64 + mf * 16 + g;
                int lr0 = r0 - m0;
                float cx0 = coords[r0*3], cy0 = coords[r0*3+1], cz0 = coords[r0*3+2];
                float cx1 = coords[(r0+8)*3], cy1 = coords[(r0+8)*3+1], cz1 = coords[(r0+8)*3+2];
#pragma unroll
                for (int nf = 0; nf < 4; nf++) {
                    int col = n0 + wn * 32 + nf * 8 + cq;
                    int h = (col - 512) >> 1;
                    int lcol = col - n0;
                    float w0 = Wrot[h*3], w1 = Wrot[h*3+1], w2 = Wrot[h*3+2];
                    float b0 = bias[col], b1 = bias[col+1];
                    float s0, c0, s1, c1;
                    __sincosf(cx0*w0 + cy0*w1 + cz0*w2, &s0, &c0);
                    __sincosf(cx1*w0 + cy1*w1 + cz1*w2, &s1, &c1);
                    float ka = acc[mf][nf][0] + b0, kb = acc[mf][nf][1] + b1;
                    st[lcol][lr0]     = __half_as_ushort(__float2half_rn(ka*c0 - kb*s0));
                    st[lcol+1][lr0]   = __half_as_ushort(__float2half_rn(ka*s0 + kb*c0));
                    ka = acc[mf][nf][2] + b0; kb = acc[mf][nf][3] + b1;
                    st[lcol][lr0+8]   = __half_as_ushort(__float2half_rn(ka*c1 - kb*s1));
                    st[lcol+1][lr0+8] = __half_as_ushort(__float2half_rn(ka*s1 + kb*c1));
                }
            }
        } else {
#pragma unroll
            for (int mf = 0; mf < 4; mf++) {
                int r0 = m0 + wm * 64 + mf * 16 + g;
                int lr0 = r0 - m0;
                float wg0 = weights[r0], wg1 = weights[r0 + 8];
#pragma unroll
                for (int nf = 0; nf < 4; nf++) {
                    int col = n0 + wn * 32 + nf * 8 + cq;
                    int lcol = col - n0;
                    float b0 = bias[col], b1 = bias[col+1];
                    st[lcol][lr0]     = __half_as_ushort(__float2half_rn((acc[mf][nf][0]+b0)*wg0));
                    st[lcol+1][lr0]   = __half_as_ushort(__float2half_rn((acc[mf][nf][1]+b1)*wg0));
                    st[lcol][lr0+8]   = __half_as_ushort(__float2half_rn((acc[mf][nf][2]+b0)*wg1));
                    st[lcol+1][lr0+8] = __half_as_ushort(__float2half_rn((acc[mf][nf][3]+b1)*wg1));
                }
            }
        }
        __syncthreads();
        // transposed coalesced write: [b, d, n]
        const int dl = tid >> 1;
        const int j0 = (tid & 1) * 64;
        const int bidx = m0 >> 12;
        const int dcol = (n0 - cbase) + dl;
        __half* dstb = (region == 1) ? g_kT_hi : g_vT_hi;
        __half* dst = dstb + ((size_t)bidx * Dd + dcol) * Nn + (m0 & 4095) + j0;
#pragma unroll
        for (int k = 0; k < 8; k++)
            *(uint4*)(dst + k * 8) = *(uint4*)&st[dl][j0 + k * 8];
    }
}

// ---------------------------------------------------------------------------
// Sum KVCH split-K partial kv slices, emit fp16 (B operand of GEMM3).
// ---------------------------------------------------------------------------
__global__ __launch_bounds__(256) void reduce_pack_kv()
{
    size_t i = ((size_t)blockIdx.x * 256 + threadIdx.x) * 2;
    size_t b   = i >> 18;
    size_t off = i & 262143;
    const float* base = g_kvp + ((size_t)b * KVCH) * 262144 + off;
    float s0 = 0.f, s1 = 0.f;
#pragma unroll
    for (int c = 0; c < KVCH; c++) {
        float2 v = *(const float2*)(base + (size_t)c * 262144);
        s0 += v.x; s1 += v.y;
    }
    size_t o = (size_t)b * 262144 + off;
    *(uint32_t*)(g_kvT_hi + o) = pack2h(s0, s1);
}

// ---------------------------------------------------------------------------
// Merged input packing: blocks [0, PHI_BLKS) pack phi -> fp16;
// blocks [PHI_BLKS, PHI_BLKS+WPART) pack permuted W + bias.
// ---------------------------------------------------------------------------
#define PHI_BLKS ((Mm*Dd)/1024)          // 16384
#define W_BLKS   ((QKVC*Dd)/1024)        // 768

__global__ __launch_bounds__(256) void pack_inputs(
    const float* __restrict__ phi,
    const float* __restrict__ Wq, const float* __restrict__ bq,
    const float* __restrict__ Wk, const float* __restrict__ bk,
    const float* __restrict__ Wv, const float* __restrict__ bv)
{
    int blk = blockIdx.x;
    if (blk < PHI_BLKS) {
        size_t i = ((size_t)blk * 256 + threadIdx.x) * 4;
        float4 x = *(const float4*)(phi + i);
        *(uint32_t*)(g_phi_hi + i)     = pack2h(x.x, x.y);
        *(uint32_t*)(g_phi_hi + i + 2) = pack2h(x.z, x.w);
    } else {
        // W part: each block covers 1024 consecutive elements = 2 rows
        size_t e = ((size_t)(blk - PHI_BLKS) * 256 + threadIdx.x) * 4;
        int r = (int)(e >> 9);          // row
        int c = (int)(e & 511);         // col
        const float* src; const float* bs; int sr;
        if (r < 512)       { src = Wq; bs = bq; int h = r >> 1;         sr = (r & 1) ? h + 256 : h; }
        else if (r < 1024) { src = Wk; bs = bk; int h = (r - 512) >> 1; sr = ((r - 512) & 1) ? h + 256 : h; }
        else               { src = Wv; bs = bv; sr = r - 1024; }
        float4 x = *(const float4*)(src + (size_t)sr * Dd + c);
        size_t o = (size_t)r * Dd + c;
        *(uint32_t*)(g_W_hi + o)     = pack2h(x.x, x.y);
        *(uint32_t*)(g_W_hi + o + 2) = pack2h(x.z, x.w);
        if (c == 0) g_bias[r] = bs[sr];
    }
}

// ---------------------------------------------------------------------------
extern "C" void kernel_launch(void* const* d_in, const int* in_sizes, int n_in,
                              void* d_out, int out_size)
{
    (void)in_sizes; (void)n_in; (void)out_size;
    const float* phi     = (const float*)d_in[0];
    const float* coords  = (const float*)d_in[1];
    const float* weights = (const float*)d_in[2];
    const float* Wq      = (const float*)d_in[3];
    const float* bq      = (const float*)d_in[4];
    const float* Wk      = (const float*)d_in[5];
    const float* bk      = (const float*)d_in[6];
    const float* Wv      = (const float*)d_in[7];
    const float* bv      = (const float*)d_in[8];
    const float* Wrot    = (const float*)d_in[9];
    float* out = (float*)d_out;

    cudaFuncSetAttribute(mma_gemm1,    cudaFuncAttributeMaxDynamicSharedMemorySize, SMEMTOT);
    cudaFuncSetAttribute(mma_gemm_qkv, cudaFuncAttributeMaxDynamicSharedMemorySize, SMEMTOT);

    __half *phi_hi, *W_hi, *q_hi, *kT_hi, *vT_hi, *kvT_hi;
    float *bias, *kvp;
    cudaGetSymbolAddress((void**)&phi_hi, g_phi_hi);
    cudaGetSymbolAddress((void**)&W_hi,   g_W_hi);
    cudaGetSymbolAddress((void**)&q_hi,   g_q_hi);
    cudaGetSymbolAddress((void**)&kT_hi,  g_kT_hi);
    cudaGetSymbolAddress((void**)&vT_hi,  g_vT_hi);
    cudaGetSymbolAddress((void**)&kvT_hi, g_kvT_hi);
    cudaGetSymbolAddress((void**)&bias,   g_bias);
    cudaGetSymbolAddress((void**)&kvp,    g_kvp);

    pack_inputs<<<PHI_BLKS + W_BLKS, 256>>>(phi, Wq, bq, Wk, bk, Wv, bv);

    // fused: qkv GEMM + bias + rope/scale/weights + fp16 pack + k/v transpose
    mma_gemm_qkv<<<dim3(QKVC/128, Mm/128, 1), 256, SMEMTOT>>>(
        phi_hi, W_hi, bias, coords, weights, Wrot);

    // kv split-K: kvp[b,chunk][e,d] = sum_{n in chunk} vT[e,n]*kT[d,n]
    mma_gemm1<<<dim3(Dd/128, Dd/128, Bb*KVCH), 256, SMEMTOT>>>(
        vT_hi, kT_hi, Nn/KVCH, Nn, 1,
        (size_t)Dd*Nn, (size_t)Dd*Nn,
        kvp, (size_t)Dd*Dd, Dd);

    reduce_pack_kv<<<(Bb * Dd * Dd) / 512, 256>>>();

    // out[m,e] = sum_d q[m,d]*kvT[e,d]
    mma_gemm1<<<dim3(Dd/128, Nn/128, Bb), 256, SMEMTOT>>>(
        q_hi, kvT_hi, Dd, Dd, 0,
        (size_t)Nn*Dd, (size_t)Dd*Dd,
        out, (size_t)Nn*Dd, Dd);
}